// round 1
// baseline (speedup 1.0000x reference)
#include <cuda_runtime.h>
#include <cuda_bf16.h>
#include <cstdint>

// Problem constants
#define B_DIM 16
#define P_DIM 87
#define K_DIM 4
#define N_DIM 32768
#define D_MODEL 256
#define HIDDEN 128
// (ATTN_SCALE / TAU) = (1/16) / 0.5 = 0.125
#define LOGIT_SCALE 0.125f

// Output layout (flattened tuple, fp32):
//   [0 .. 1392)        human_probs  (16*87)
//   [1392 .. 2784)     human_logits (16*87)
//   [2784 .. 2976)     object_coords (16*4*3)
#define OUT_PROBS 0
#define OUT_LOGITS 1392
#define OUT_COORDS 2784

// Scratch (no allocations allowed -> __device__ globals)
__device__ float g_q[B_DIM * K_DIM * D_MODEL];   // projected queries
__device__ float g_acc[B_DIM * K_DIM * 4];       // per (b,k): sumw, sx, sy, sz

// ---------------------------------------------------------------------------
// Kernel 1: human MLP head (blocks 0..1391) + q projection (blocks 1392..1455)
// Also zeroes g_acc (done by q-proj block row==0).
// ---------------------------------------------------------------------------
__global__ void head_qproj_kernel(const float* __restrict__ hq,
                                  const float* __restrict__ oq,
                                  const float* __restrict__ W1,
                                  const float* __restrict__ b1,
                                  const float* __restrict__ W2,
                                  const float* __restrict__ b2,
                                  const float* __restrict__ Wq,
                                  const float* __restrict__ bq,
                                  float* __restrict__ out) {
    __shared__ float shx[D_MODEL];
    __shared__ float red[HIDDEN];
    const int blk = blockIdx.x;
    const int t = threadIdx.x;

    if (blk < B_DIM * P_DIM) {
        // ---- human head: one block per (b,p) row ----
        const float* x = hq + (size_t)blk * D_MODEL;
        shx[t] = x[t];
        __syncthreads();
        if (t < HIDDEN) {
            float acc = b1[t];
#pragma unroll 8
            for (int i = 0; i < D_MODEL; i++)
                acc = fmaf(shx[i], W1[i * HIDDEN + t], acc);
            acc = fmaxf(acc, 0.0f);
            red[t] = acc * W2[t];
        }
        __syncthreads();
        if (t < 64) red[t] += red[t + 64];
        __syncthreads();
        if (t < 32) {
            float v = red[t] + red[t + 32];
#pragma unroll
            for (int off = 16; off > 0; off >>= 1)
                v += __shfl_xor_sync(0xffffffffu, v, off);
            if (t == 0) {
                float logit = v + b2[0];
                out[OUT_LOGITS + blk] = logit;
                out[OUT_PROBS + blk] = 1.0f / (1.0f + __expf(-logit));
            }
        }
    } else {
        // ---- q projection: one block per (b,k) row ----
        const int row = blk - B_DIM * P_DIM;  // 0..63
        const float* x = oq + (size_t)row * D_MODEL;
        shx[t] = x[t];
        if (row == 0) g_acc[t] = 0.0f;  // 256 floats, exactly blockDim
        __syncthreads();
        float acc = bq[t];
#pragma unroll 8
        for (int i = 0; i < D_MODEL; i++)
            acc = fmaf(shx[i], Wq[i * D_MODEL + t], acc);
        g_q[row * D_MODEL + t] = acc;
    }
}

// ---------------------------------------------------------------------------
// Kernel 2: attention pooling mainloop. Warp-per-row over object_feats.
// grid = (N/CHUNK, B), block = 256 (8 warps, 32 rows/warp).
// One-pass softmax accumulation (no max subtraction; logits bounded ~|6|).
// ---------------------------------------------------------------------------
#define CHUNK 256
#define ROWS_PER_WARP (CHUNK / 8)

__global__ void __launch_bounds__(256, 4)
attn_pool_kernel(const float* __restrict__ feats,
                 const float* __restrict__ xyz) {
    const int b = blockIdx.y;
    const int base = blockIdx.x * CHUNK;
    const int w = threadIdx.x >> 5;
    const int lane = threadIdx.x & 31;

    // q for this batch in registers: lane covers elems [4*lane,4*lane+4) and
    // [128+4*lane, 128+4*lane+4) of each of the 4 query vectors.
    const float4* q4 = reinterpret_cast<const float4*>(g_q + (size_t)b * K_DIM * D_MODEL);
    float4 qa[K_DIM], qb[K_DIM];
#pragma unroll
    for (int k = 0; k < K_DIM; k++) {
        qa[k] = q4[k * 64 + lane];
        qb[k] = q4[k * 64 + 32 + lane];
    }

    const float4* f4 = reinterpret_cast<const float4*>(
        feats + ((size_t)b * N_DIM + base) * D_MODEL);
    const float* xp_base = xyz + ((size_t)b * N_DIM + base) * 3;

    float aw = 0.0f, ax = 0.0f, ay = 0.0f, az = 0.0f;

    const int r0 = w * ROWS_PER_WARP;
#pragma unroll 4
    for (int r = 0; r < ROWS_PER_WARP; r++) {
        const int row = r0 + r;
        const float4 fa = f4[(size_t)row * 64 + lane];
        const float4 fb = f4[(size_t)row * 64 + 32 + lane];

        float p0, p1, p2, p3;
        {
            p0 = fa.x * qa[0].x; p0 = fmaf(fa.y, qa[0].y, p0);
            p0 = fmaf(fa.z, qa[0].z, p0); p0 = fmaf(fa.w, qa[0].w, p0);
            p0 = fmaf(fb.x, qb[0].x, p0); p0 = fmaf(fb.y, qb[0].y, p0);
            p0 = fmaf(fb.z, qb[0].z, p0); p0 = fmaf(fb.w, qb[0].w, p0);

            p1 = fa.x * qa[1].x; p1 = fmaf(fa.y, qa[1].y, p1);
            p1 = fmaf(fa.z, qa[1].z, p1); p1 = fmaf(fa.w, qa[1].w, p1);
            p1 = fmaf(fb.x, qb[1].x, p1); p1 = fmaf(fb.y, qb[1].y, p1);
            p1 = fmaf(fb.z, qb[1].z, p1); p1 = fmaf(fb.w, qb[1].w, p1);

            p2 = fa.x * qa[2].x; p2 = fmaf(fa.y, qa[2].y, p2);
            p2 = fmaf(fa.z, qa[2].z, p2); p2 = fmaf(fa.w, qa[2].w, p2);
            p2 = fmaf(fb.x, qb[2].x, p2); p2 = fmaf(fb.y, qb[2].y, p2);
            p2 = fmaf(fb.z, qb[2].z, p2); p2 = fmaf(fb.w, qb[2].w, p2);

            p3 = fa.x * qa[3].x; p3 = fmaf(fa.y, qa[3].y, p3);
            p3 = fmaf(fa.z, qa[3].z, p3); p3 = fmaf(fa.w, qa[3].w, p3);
            p3 = fmaf(fb.x, qb[3].x, p3); p3 = fmaf(fb.y, qb[3].y, p3);
            p3 = fmaf(fb.z, qb[3].z, p3); p3 = fmaf(fb.w, qb[3].w, p3);
        }

        // Full butterfly warp reduction for all 4 logits
#pragma unroll
        for (int off = 16; off > 0; off >>= 1) {
            p0 += __shfl_xor_sync(0xffffffffu, p0, off);
            p1 += __shfl_xor_sync(0xffffffffu, p1, off);
            p2 += __shfl_xor_sync(0xffffffffu, p2, off);
            p3 += __shfl_xor_sync(0xffffffffu, p3, off);
        }

        // Lanes 0..3 each own one k: exp + weighted xyz accumulation
        if (lane < K_DIM) {
            float p = (lane == 0) ? p0 : (lane == 1) ? p1 : (lane == 2) ? p2 : p3;
            float wgt = __expf(p * LOGIT_SCALE);
            const float* xp = xp_base + (size_t)row * 3;
            aw += wgt;
            ax = fmaf(wgt, xp[0], ax);
            ay = fmaf(wgt, xp[1], ay);
            az = fmaf(wgt, xp[2], az);
        }
    }

    if (lane < K_DIM) {
        float* g = g_acc + ((size_t)b * K_DIM + lane) * 4;
        atomicAdd(g + 0, aw);
        atomicAdd(g + 1, ax);
        atomicAdd(g + 2, ay);
        atomicAdd(g + 3, az);
    }
}

// ---------------------------------------------------------------------------
// Kernel 3: finalize coords = (sum w*xyz) / (sum w)
// ---------------------------------------------------------------------------
__global__ void finalize_kernel(float* __restrict__ out) {
    const int t = threadIdx.x;  // 0..63 = (b*4 + k)
    if (t < B_DIM * K_DIM) {
        const float* g = g_acc + (size_t)t * 4;
        const float inv = 1.0f / g[0];
        out[OUT_COORDS + t * 3 + 0] = g[1] * inv;
        out[OUT_COORDS + t * 3 + 1] = g[2] * inv;
        out[OUT_COORDS + t * 3 + 2] = g[3] * inv;
    }
}

// ---------------------------------------------------------------------------
extern "C" void kernel_launch(void* const* d_in, const int* in_sizes, int n_in,
                              void* d_out, int out_size) {
    const float* hq    = (const float*)d_in[0];  // (16, 87, 256)
    const float* oq    = (const float*)d_in[1];  // (16, 4, 256)
    const float* feats = (const float*)d_in[2];  // (16, 32768, 256)
    const float* xyz   = (const float*)d_in[3];  // (16, 32768, 3)
    const float* W1    = (const float*)d_in[4];  // (256, 128)
    const float* b1    = (const float*)d_in[5];  // (128,)
    const float* W2    = (const float*)d_in[6];  // (128, 1)
    const float* b2    = (const float*)d_in[7];  // (1,)
    const float* Wq    = (const float*)d_in[8];  // (256, 256)
    const float* bq    = (const float*)d_in[9];  // (256,)
    float* out = (float*)d_out;

    // 1392 human-head blocks + 64 q-proj blocks (also zeroes accumulators)
    head_qproj_kernel<<<B_DIM * P_DIM + B_DIM * K_DIM, 256>>>(
        hq, oq, W1, b1, W2, b2, Wq, bq, out);

    dim3 grid(N_DIM / CHUNK, B_DIM);  // (128, 16)
    attn_pool_kernel<<<grid, 256>>>(feats, xyz);

    finalize_kernel<<<1, 64>>>(out);
}